// round 3
// baseline (speedup 1.0000x reference)
#include <cuda_runtime.h>
#include <math.h>

#define H_ 256
#define W_ 256
#define CIN_ 128
#define B_ 2
#define K_ 4
#define HWSZ (H_ * W_)

typedef unsigned long long ull;

// ---------------- scratch (device globals; no allocation allowed) ----------------
__device__ float g_t1[B_ * CIN_ * HWSZ];    // gelu(conv3x3(query, ow1))
__device__ float g_off[B_ * 2 * K_ * HWSZ]; // offsets
__device__ float g_w1[B_ * 32 * HWSZ];      // gelu(conv3x3(query, ww1))
__device__ float g_agg[B_ * CIN_ * HWSZ];   // sampled+weighted aggregate

__device__ __forceinline__ float gelu_f(float x) {
    return 0.5f * x * (1.0f + erff(x * 0.70710678118654752440f));
}

// ---------------- packed f32x2 helpers (FFMA2: 2 FMAs per issue) ----------------
__device__ __forceinline__ ull pack2(float lo, float hi) {
    ull r;
    asm("mov.b64 %0, {%1, %2};" : "=l"(r) : "f"(lo), "f"(hi));
    return r;
}
__device__ __forceinline__ void unpack2(ull v, float& lo, float& hi) {
    asm("mov.b64 {%0, %1}, %2;" : "=f"(lo), "=f"(hi) : "l"(v));
}
__device__ __forceinline__ ull ffma2(ull a, ull b, ull c) {
    ull d;
    asm("fma.rn.f32x2 %0, %1, %2, %3;" : "=l"(d) : "l"(a), "l"(b), "l"(c));
    return d;
}

// ---------------- 3x3 conv, Cin=128, pad=1, optional GELU, FFMA2 inner ----------
// R1 geometry: tile 32 wide x 4 high, COUT_TILE outputs, 256 threads, cin chunks 8.
// Thread: 4 pixels (x strided by 8) paired into 2 f32x2 accumulators x NCO couts.
// Weights staged duplicated (w,w) as 64-bit -> broadcast LDS.64 in hot loop.
template <int COUT_TILE, int NCO, bool DO_GELU>
__global__ __launch_bounds__(256) void conv3x3_kernel(
    const float* __restrict__ in, const float* __restrict__ wt,
    const float* __restrict__ bias, float* __restrict__ out, int Cout)
{
    constexpr int TW = 32, TH = 4, CINC = 8;
    constexpr int SW = 40;  // 40 % 32 == 8 -> conflict-free for stride-8 access
    __shared__ float s_in[CINC * (TH + 2) * SW];   // 7.5 KB
    __shared__ ull s_w[COUT_TILE * CINC * 9];      // dup weights (36.9 KB @ 64)

    const int tx = blockIdx.x & 7;          // W_/TW = 8
    const int ty = blockIdx.x >> 3;         // H_/TH = 64
    const int x0 = tx * TW, y0 = ty * TH;
    const int b = blockIdx.z;
    const int coB = blockIdx.y * COUT_TILE;
    const int tid = threadIdx.x;
    const int pg = tid & 31;
    const int cog = tid >> 5;               // 8 cout groups (warp-uniform)
    const int gx = pg & 7;
    const int py = pg >> 3;
    const int co_base = cog * NCO;

    ull acc[2][NCO];
#pragma unroll
    for (int jj = 0; jj < 2; jj++)
#pragma unroll
        for (int c = 0; c < NCO; c++) acc[jj][c] = 0ull;

    const float* inb = in + (size_t)b * CIN_ * HWSZ;

    for (int ci0 = 0; ci0 < CIN_; ci0 += CINC) {
        // stage input tile (zero padded): 8*6*34 = 1632 elems
        for (int idx = tid; idx < CINC * (TH + 2) * (TW + 2); idx += 256) {
            int c = idx / ((TH + 2) * (TW + 2));
            int rem = idx % ((TH + 2) * (TW + 2));
            int r = rem / (TW + 2), col = rem % (TW + 2);
            int iy = y0 + r - 1, ix = x0 + col - 1;
            float v = 0.f;
            if (iy >= 0 && iy < H_ && ix >= 0 && ix < W_)
                v = inb[(size_t)(ci0 + c) * HWSZ + iy * W_ + ix];
            s_in[(c * (TH + 2) + r) * SW + col] = v;
        }
        // stage weights duplicated: [COUT_TILE][CINC*9] of (w,w)
        for (int idx = tid; idx < COUT_TILE * CINC * 9; idx += 256) {
            int co = idx / (CINC * 9);
            int rem = idx % (CINC * 9);
            float w = wt[(size_t)(coB + co) * CIN_ * 9 + ci0 * 9 + rem];
            s_w[idx] = pack2(w, w);
        }
        __syncthreads();

#pragma unroll 2
        for (int cc = 0; cc < CINC; ++cc) {
            const float* si = &s_in[(cc * (TH + 2) + py) * SW + gx];
            const ull* swp = &s_w[co_base * (CINC * 9) + cc * 9];
#pragma unroll
            for (int ky = 0; ky < 3; ++ky) {
#pragma unroll
                for (int kx = 0; kx < 3; ++kx) {
                    float f0 = si[ky * SW + kx];
                    float f1 = si[ky * SW + kx + 8];
                    float f2 = si[ky * SW + kx + 16];
                    float f3 = si[ky * SW + kx + 24];
                    ull p0 = pack2(f0, f1);
                    ull p1 = pack2(f2, f3);
#pragma unroll
                    for (int c = 0; c < NCO; c++) {
                        ull wv = swp[c * (CINC * 9) + ky * 3 + kx];
                        acc[0][c] = ffma2(p0, wv, acc[0][c]);
                        acc[1][c] = ffma2(p1, wv, acc[1][c]);
                    }
                }
            }
        }
        __syncthreads();
    }

    const int yy = y0 + py;
#pragma unroll
    for (int c = 0; c < NCO; c++) {
        int co = coB + co_base + c;
        float bv = bias[co];
        float* ob = out + ((size_t)b * Cout + co) * HWSZ + yy * W_ + x0 + gx;
        float v0, v1, v2, v3;
        unpack2(acc[0][c], v0, v1);
        unpack2(acc[1][c], v2, v3);
        v0 += bv; v1 += bv; v2 += bv; v3 += bv;
        if (DO_GELU) { v0 = gelu_f(v0); v1 = gelu_f(v1); v2 = gelu_f(v2); v3 = gelu_f(v3); }
        ob[0]  = v0;
        ob[8]  = v1;
        ob[16] = v2;
        ob[24] = v3;
    }
}

// ---------------- sampler: wlog(1x1)+softmax, offsets->positions, K=4 bilinear ----
__global__ __launch_bounds__(256) void sampler_kernel(
    const float* __restrict__ key, const float* __restrict__ ww2,
    const float* __restrict__ wb2)
{
    __shared__ float s_ww2[K_ * 32];
    __shared__ float s_wb2[K_];
    __shared__ float s_logit[K_][64];
    __shared__ int   s_o[K_][4][64];
    __shared__ float s_wt[K_][4][64];

    const int b = blockIdx.z, y = blockIdx.y, x0 = blockIdx.x * 64;
    const int tid = threadIdx.x;
    if (tid < K_ * 32) s_ww2[tid] = ww2[tid];
    if (tid < K_) s_wb2[tid] = wb2[tid];
    __syncthreads();

    const int px = tid & 63;
    const int k = tid >> 6;
    const int x = x0 + px;

    const float* offb = g_off + (size_t)b * 2 * K_ * HWSZ + y * W_ + x;
    float ox = offb[(size_t)(2 * k) * HWSZ];
    float oy = offb[(size_t)(2 * k + 1) * HWSZ];

    const float* w1b = g_w1 + (size_t)b * 32 * HWSZ + y * W_ + x;
    float l = s_wb2[k];
#pragma unroll 8
    for (int c = 0; c < 32; c++) l = fmaf(s_ww2[k * 32 + c], w1b[(size_t)c * HWSZ], l);
    s_logit[k][px] = l;

    float bx = -1.f + 2.f * x * (1.f / (W_ - 1));
    float by = -1.f + 2.f * y * (1.f / (H_ - 1));
    float gxn = fminf(fmaxf(bx + ox * (2.f / W_), -1.f), 1.f);
    float gyn = fminf(fmaxf(by + oy * (2.f / H_), -1.f), 1.f);
    float pxf = (gxn + 1.f) * 0.5f * (W_ - 1);
    float pyf = (gyn + 1.f) * 0.5f * (H_ - 1);
    pxf = fminf(fmaxf(pxf, 0.f), (float)(W_ - 1));
    pyf = fminf(fmaxf(pyf, 0.f), (float)(H_ - 1));
    int ix0 = min((int)floorf(pxf), W_ - 1);
    int iy0 = min((int)floorf(pyf), H_ - 1);
    int ix1 = min(ix0 + 1, W_ - 1);
    int iy1 = min(iy0 + 1, H_ - 1);
    float fx = pxf - (float)ix0, fy = pyf - (float)iy0;
    __syncthreads();

    float m = fmaxf(fmaxf(s_logit[0][px], s_logit[1][px]),
                    fmaxf(s_logit[2][px], s_logit[3][px]));
    float se = 0.f;
#pragma unroll
    for (int q = 0; q < K_; q++) se += expf(s_logit[q][px] - m);
    float wk = expf(l - m) / se;

    s_o[k][0][px] = iy0 * W_ + ix0;
    s_o[k][1][px] = iy0 * W_ + ix1;
    s_o[k][2][px] = iy1 * W_ + ix0;
    s_o[k][3][px] = iy1 * W_ + ix1;
    s_wt[k][0][px] = wk * (1.f - fx) * (1.f - fy);
    s_wt[k][1][px] = wk * fx * (1.f - fy);
    s_wt[k][2][px] = wk * (1.f - fx) * fy;
    s_wt[k][3][px] = wk * fx * fy;
    __syncthreads();

    int o[K_][4]; float w[K_][4];
#pragma unroll
    for (int q = 0; q < K_; q++)
#pragma unroll
        for (int t = 0; t < 4; t++) { o[q][t] = s_o[q][t][px]; w[q][t] = s_wt[q][t][px]; }

    const int cq = tid >> 6;
    const float* keyb = key + (size_t)b * CIN_ * HWSZ;
    float* aggb = g_agg + (size_t)b * CIN_ * HWSZ + y * W_ + x;
    for (int it = 0; it < 32; ++it) {
        int c = it * 4 + cq;
        const float* kp = keyb + (size_t)c * HWSZ;
        float a = 0.f;
#pragma unroll
        for (int q = 0; q < K_; q++) {
            a = fmaf(kp[o[q][0]], w[q][0], a);
            a = fmaf(kp[o[q][1]], w[q][1], a);
            a = fmaf(kp[o[q][2]], w[q][2], a);
            a = fmaf(kp[o[q][3]], w[q][3], a);
        }
        aggb[(size_t)c * HWSZ] = a;
    }
}

// ---------------- fusion: conv1x1 -> gelu -> conv1x1, residual + 0.3, FFMA2 -----
__global__ __launch_bounds__(256) void fusion_kernel(
    const float* __restrict__ query,
    const float* __restrict__ fw1, const float* __restrict__ fb1,
    const float* __restrict__ fw2, const float* __restrict__ fb2,
    float* __restrict__ out)
{
    constexpr int PX = 64, CIC = 8, SXS = 64;
    __shared__ float s_x[128 * SXS];      // 32 KB intermediate
    __shared__ float s_in[CIC * PX];      // 2 KB
    __shared__ ull   s_w[128 * CIC];      // 8 KB dup weights

    const int b = blockIdx.y;
    const int p0 = blockIdx.x * PX;
    const int tid = threadIdx.x;
    const int pg = tid & 15;
    const int cog = tid >> 4;
    const int co0 = cog * 8;

    const float* aggb = g_agg + (size_t)b * 128 * HWSZ + p0;

    ull acc[2][8];
#pragma unroll
    for (int j = 0; j < 2; j++)
#pragma unroll
        for (int c = 0; c < 8; c++) acc[j][c] = 0ull;

    for (int ci0 = 0; ci0 < 128; ci0 += CIC) {
        for (int idx = tid; idx < CIC * PX; idx += 256) {
            int c = idx >> 6, p = idx & 63;
            s_in[idx] = aggb[(size_t)(ci0 + c) * HWSZ + p];
        }
        for (int idx = tid; idx < 128 * CIC; idx += 256) {
            int co = idx / CIC, ci = idx % CIC;
            float w = fw1[co * 128 + ci0 + ci];
            s_w[idx] = pack2(w, w);
        }
        __syncthreads();
#pragma unroll
        for (int ci = 0; ci < CIC; ++ci) {
            ull p01 = pack2(s_in[ci * PX + pg], s_in[ci * PX + pg + 16]);
            ull p23 = pack2(s_in[ci * PX + pg + 32], s_in[ci * PX + pg + 48]);
#pragma unroll
            for (int c = 0; c < 8; c++) {
                ull wv = s_w[(co0 + c) * CIC + ci];
                acc[0][c] = ffma2(p01, wv, acc[0][c]);
                acc[1][c] = ffma2(p23, wv, acc[1][c]);
            }
        }
        __syncthreads();
    }
#pragma unroll
    for (int c = 0; c < 8; c++) {
        float bv = fb1[co0 + c];
        float v0, v1, v2, v3;
        unpack2(acc[0][c], v0, v1);
        unpack2(acc[1][c], v2, v3);
        s_x[(co0 + c) * SXS + pg]      = gelu_f(v0 + bv);
        s_x[(co0 + c) * SXS + pg + 16] = gelu_f(v1 + bv);
        s_x[(co0 + c) * SXS + pg + 32] = gelu_f(v2 + bv);
        s_x[(co0 + c) * SXS + pg + 48] = gelu_f(v3 + bv);
    }
    __syncthreads();

    ull acc2[2][8];
#pragma unroll
    for (int j = 0; j < 2; j++)
#pragma unroll
        for (int c = 0; c < 8; c++) acc2[j][c] = 0ull;

    for (int ci0 = 0; ci0 < 128; ci0 += CIC) {
        for (int idx = tid; idx < 128 * CIC; idx += 256) {
            int co = idx / CIC, ci = idx % CIC;
            float w = fw2[co * 128 + ci0 + ci];
            s_w[idx] = pack2(w, w);
        }
        __syncthreads();
#pragma unroll
        for (int ci = 0; ci < CIC; ++ci) {
            const float* sx = &s_x[(ci0 + ci) * SXS + pg];
            ull p01 = pack2(sx[0], sx[16]);
            ull p23 = pack2(sx[32], sx[48]);
#pragma unroll
            for (int c = 0; c < 8; c++) {
                ull wv = s_w[(co0 + c) * CIC + ci];
                acc2[0][c] = ffma2(p01, wv, acc2[0][c]);
                acc2[1][c] = ffma2(p23, wv, acc2[1][c]);
            }
        }
        __syncthreads();
    }

    const float* qb = query + (size_t)b * 128 * HWSZ + p0;
    float* ob = out + (size_t)b * 128 * HWSZ + p0;
#pragma unroll
    for (int c = 0; c < 8; c++) {
        float bv = fb2[co0 + c];
        float v0, v1, v2, v3;
        unpack2(acc2[0][c], v0, v1);
        unpack2(acc2[1][c], v2, v3);
        size_t base = (size_t)(co0 + c) * HWSZ + pg;
        ob[base]      = qb[base]      + 0.3f * (v0 + bv);
        ob[base + 16] = qb[base + 16] + 0.3f * (v1 + bv);
        ob[base + 32] = qb[base + 32] + 0.3f * (v2 + bv);
        ob[base + 48] = qb[base + 48] + 0.3f * (v3 + bv);
    }
}

// ---------------- launch ----------------
extern "C" void kernel_launch(void* const* d_in, const int* in_sizes, int n_in,
                              void* d_out, int out_size)
{
    const float* query = (const float*)d_in[0];
    const float* key   = (const float*)d_in[1];
    const float* ow1 = (const float*)d_in[2];
    const float* ob1 = (const float*)d_in[3];
    const float* ow2 = (const float*)d_in[4];
    const float* ob2 = (const float*)d_in[5];
    const float* ww1 = (const float*)d_in[6];
    const float* wb1 = (const float*)d_in[7];
    const float* ww2 = (const float*)d_in[8];
    const float* wb2 = (const float*)d_in[9];
    const float* fw1 = (const float*)d_in[10];
    const float* fb1 = (const float*)d_in[11];
    const float* fw2 = (const float*)d_in[12];
    const float* fb2 = (const float*)d_in[13];
    float* out = (float*)d_out;

    float *t1p, *offp, *w1p;
    cudaGetSymbolAddress((void**)&t1p, g_t1);
    cudaGetSymbolAddress((void**)&offp, g_off);
    cudaGetSymbolAddress((void**)&w1p, g_w1);

    dim3 blk(256);
    // t1 = gelu(conv3x3(query, ow1))   Cout=128
    conv3x3_kernel<64, 8, true><<<dim3(512, 2, B_), blk>>>(query, ow1, ob1, t1p, 128);
    // offsets = conv3x3(t1, ow2)       Cout=8
    conv3x3_kernel<8, 1, false><<<dim3(512, 1, B_), blk>>>(t1p, ow2, ob2, offp, 8);
    // w1 = gelu(conv3x3(query, ww1))   Cout=32
    conv3x3_kernel<32, 4, true><<<dim3(512, 1, B_), blk>>>(query, ww1, wb1, w1p, 32);
    // sampler: wlog 1x1 + softmax + deformable bilinear gather -> g_agg
    sampler_kernel<<<dim3(W_ / 64, H_, B_), blk>>>(key, ww2, wb2);
    // fusion convs + residual
    fusion_kernel<<<dim3(HWSZ / 64, B_), blk>>>(query, fw1, fb1, fw2, fb2, out);
}

// round 5
// speedup vs baseline: 1.3705x; 1.3705x over previous
#include <cuda_runtime.h>
#include <cuda_bf16.h>
#include <math.h>

#define H_ 256
#define W_ 256
#define CIN_ 128
#define B_ 2
#define K_ 4
#define HWSZ (H_ * W_)

typedef unsigned long long ull;
typedef unsigned int u32;

// ---------------- scratch (device globals; no allocation allowed) ----------------
__device__ float g_t1[B_ * CIN_ * HWSZ];    // gelu(conv3x3(query, ow1))
__device__ float g_off[B_ * 2 * K_ * HWSZ]; // offsets
__device__ float g_w1[B_ * 32 * HWSZ];      // gelu(conv3x3(query, ww1))
__device__ float g_agg[B_ * CIN_ * HWSZ];   // sampled+weighted aggregate
// conv1 weights, hi/lo bf16 split, fragment-permuted u64 layout:
// 12 blocks (4 cin-chunks x 3 ky) x 128 cout rows x 52 u64 (48 data + 4 pad)
__device__ ull g_wA[12 * 128 * 52];

__device__ __forceinline__ float gelu_f(float x) {
    return 0.5f * x * (1.0f + erff(x * 0.70710678118654752440f));
}

__device__ __forceinline__ u32 pack_bf16x2(float a, float b) {
    __nv_bfloat16 ha = __float2bfloat16(a), hb = __float2bfloat16(b);
    unsigned short ua = *(unsigned short*)&ha, ub = *(unsigned short*)&hb;
    return (u32)ua | ((u32)ub << 16);
}

// ---------------- prep: split conv1 weights into hi/lo bf16 fragments ------------
// Layout per block row (cout): 12 groups of 4 u64 slots.
// Groups 0..5 = hi (segment k-pairs 0..47), 6..11 = lo.
// Slot (g, tig): low u32 = logical word w=tig of group, high u32 = w=tig+4.
// Logical pair jj (0..47): k0 = 2*jj, kx = jj>>4, cin = k0 & 31.
__global__ void prep_wA_kernel(const float* __restrict__ wt) {
    int idx = blockIdx.x * 256 + threadIdx.x;   // 12*128*48 = 73728
    if (idx >= 12 * 128 * 48) return;
    int blk = idx / (128 * 48);
    int rem = idx % (128 * 48);
    int cout = rem / 48;
    int slot = rem % 48;
    int g = slot >> 2, tig = slot & 3;
    int chunk = blk / 3, ky = blk % 3;
    bool is_lo = (g >= 6);
    int gg = is_lo ? g - 6 : g;

    u32 words[2];
#pragma unroll
    for (int h = 0; h < 2; ++h) {
        int w = tig + 4 * h;
        int jj = gg * 8 + w;
        int kx = jj >> 4;
        int c0 = (2 * jj) & 31;
        float w0 = wt[((size_t)(cout * 128 + chunk * 32 + c0) * 3 + ky) * 3 + kx];
        float w1 = wt[((size_t)(cout * 128 + chunk * 32 + c0 + 1) * 3 + ky) * 3 + kx];
        if (!is_lo) {
            words[h] = pack_bf16x2(w0, w1);
        } else {
            __nv_bfloat16 h0 = __float2bfloat16(w0), h1 = __float2bfloat16(w1);
            words[h] = pack_bf16x2(w0 - __bfloat162float(h0),
                                   w1 - __bfloat162float(h1));
        }
    }
    g_wA[(size_t)blk * 128 * 52 + cout * 52 + slot] =
        (ull)words[0] | ((ull)words[1] << 32);
}

// ---------------- conv1 via mma.sync bf16 (3-term hi/lo) -------------------------
// CTA: 64 px x 2 output rows x 128 couts. 8 warps, warp w -> couts 16w..16w+15.
// SMEM: 4 B row-tiles (64 n x 52 u64) + A tile (128 x 52 u64, reused as strip).
#define BT_U64 3328                       // 64 * 52
#define A_U64  6656                       // 128 * 52
#define SMEM_MMA ((4 * BT_U64 + A_U64) * 8)   // 159744 B

__global__ __launch_bounds__(256) void conv1_mma_kernel(
    const float* __restrict__ q, const float* __restrict__ bias,
    float* __restrict__ out)
{
    extern __shared__ __align__(16) ull smem[];
    ull* Bsm = smem;
    ull* Asm = smem + 4 * BT_U64;
    float* strip = (float*)Asm;           // 66 x 36 floats (9504 B)

    const int tid = threadIdx.x;
    const int lane = tid & 31, wid = tid >> 5;
    const int gr = lane >> 2, tig = lane & 3;
    const int m0 = wid * 16;
    const int x0 = blockIdx.x * 64, y0 = blockIdx.y * 2, b = blockIdx.z;

    float acc[2][8][4];
#pragma unroll
    for (int ry = 0; ry < 2; ++ry)
#pragma unroll
        for (int nt = 0; nt < 8; ++nt)
#pragma unroll
            for (int i = 0; i < 4; ++i) acc[ry][nt][i] = 0.f;

    const float* inb = q + (size_t)b * CIN_ * HWSZ;

    for (int chunk = 0; chunk < 4; ++chunk) {
        __syncthreads();   // protect B tiles + A/strip region from prior reads
        // ---- build 4 B row-tiles (input rows y0-1 .. y0+2), cin chunk ----
        for (int t = 0; t < 4; ++t) {
            int r = y0 + t - 1;
            bool vr = (r >= 0 && r < H_);
            for (int idx = tid; idx < 32 * 66; idx += 256) {
                int c = idx / 66, xo = idx % 66;
                int x = x0 + xo - 1;
                float v = 0.f;
                if (vr && x >= 0 && x < W_)
                    v = inb[(size_t)(chunk * 32 + c) * HWSZ + r * W_ + x];
                strip[xo * 36 + c] = v;
            }
            __syncthreads();
            u32* bt = (u32*)(Bsm + t * BT_U64);
            for (int idx = tid; idx < 64 * 48; idx += 256) {
                int n = idx / 48, j = idx % 48;
                int kx = j >> 4;
                int c0 = (2 * j) & 31;
                float v0 = strip[(n + kx) * 36 + c0];
                float v1 = strip[(n + kx) * 36 + c0 + 1];
                __nv_bfloat16 h0 = __float2bfloat16(v0);
                __nv_bfloat16 h1 = __float2bfloat16(v1);
                u32 hw = pack_bf16x2(v0, v1);
                u32 lw = pack_bf16x2(v0 - __bfloat162float(h0),
                                     v1 - __bfloat162float(h1));
                int g = j >> 3, ww = j & 7;
                int posh = g * 8 + 2 * (ww & 3) + (ww >> 2);
                bt[n * 104 + posh]      = hw;
                bt[n * 104 + posh + 48] = lw;
            }
            __syncthreads();
        }
        // ---- ky taps: stage A(chunk,ky), run 3-term MMA over k ----
        for (int ky = 0; ky < 3; ++ky) {
            const uint4* srcw = (const uint4*)(g_wA + (size_t)(chunk * 3 + ky) * A_U64);
            uint4* dstw = (uint4*)Asm;
#pragma unroll 4
            for (int i = tid; i < A_U64 / 2; i += 256) dstw[i] = srcw[i];
            __syncthreads();

            const ull* Arow0 = Asm + (m0 + gr) * 52 + tig;
            const ull* Arow1 = Asm + (m0 + gr + 8) * 52 + tig;
#pragma unroll
            for (int seg = 0; seg < 3; ++seg) {
                const int ao = (seg < 2) ? 0 : 24;   // u64 offset: lo A segment
                const int bo = (seg == 1) ? 24 : 0;  // u64 offset: lo B segment
#pragma unroll
                for (int s6 = 0; s6 < 6; ++s6) {
                    ull a01 = Arow0[ao + s6 * 4];
                    ull a23 = Arow1[ao + s6 * 4];
                    u32 a0 = (u32)a01, a2 = (u32)(a01 >> 32);
                    u32 a1 = (u32)a23, a3 = (u32)(a23 >> 32);
#pragma unroll
                    for (int ry = 0; ry < 2; ++ry) {
                        const ull* Bt = Bsm + (ry + ky) * BT_U64
                                      + gr * 52 + tig + bo + s6 * 4;
#pragma unroll
                        for (int nt = 0; nt < 8; ++nt) {
                            ull b01 = Bt[nt * 8 * 52];
                            u32 b0 = (u32)b01, b1 = (u32)(b01 >> 32);
                            asm volatile(
                                "mma.sync.aligned.m16n8k16.row.col.f32.bf16.bf16.f32 "
                                "{%0,%1,%2,%3}, {%4,%5,%6,%7}, {%8,%9}, {%0,%1,%2,%3};"
                                : "+f"(acc[ry][nt][0]), "+f"(acc[ry][nt][1]),
                                  "+f"(acc[ry][nt][2]), "+f"(acc[ry][nt][3])
                                : "r"(a0), "r"(a1), "r"(a2), "r"(a3),
                                  "r"(b0), "r"(b1));
                        }
                    }
                }
            }
            __syncthreads();
        }
    }

    // ---- epilogue: bias + gelu, store D[m=cout][n=px] ----
    float bv0 = bias[m0 + gr];
    float bv1 = bias[m0 + gr + 8];
#pragma unroll
    for (int ry = 0; ry < 2; ++ry) {
        int y = y0 + ry;
#pragma unroll
        for (int nt = 0; nt < 8; ++nt) {
            int px = x0 + nt * 8 + 2 * tig;
            float2 o0, o1;
            o0.x = gelu_f(acc[ry][nt][0] + bv0);
            o0.y = gelu_f(acc[ry][nt][1] + bv0);
            o1.x = gelu_f(acc[ry][nt][2] + bv1);
            o1.y = gelu_f(acc[ry][nt][3] + bv1);
            *(float2*)(out + ((size_t)b * 128 + m0 + gr) * HWSZ + y * W_ + px) = o0;
            *(float2*)(out + ((size_t)b * 128 + m0 + gr + 8) * HWSZ + y * W_ + px) = o1;
        }
    }
}

// ---------------- generic 3x3 conv (scalar fp32, R1-proven) ---------------------
template <int COUT_TILE, int NCO, bool DO_GELU>
__global__ __launch_bounds__(256) void conv3x3_kernel(
    const float* __restrict__ in, const float* __restrict__ wt,
    const float* __restrict__ bias, float* __restrict__ out, int Cout)
{
    constexpr int TW = 32, TH = 4, CINC = 8;
    constexpr int SW = 40;
    __shared__ float s_in[CINC * (TH + 2) * SW];
    __shared__ float s_w[COUT_TILE * CINC * 9];

    const int tx = blockIdx.x & 7;
    const int ty = blockIdx.x >> 3;
    const int x0 = tx * TW, y0 = ty * TH;
    const int b = blockIdx.z;
    const int coB = blockIdx.y * COUT_TILE;
    const int tid = threadIdx.x;
    const int pg = tid & 31;
    const int cog = tid >> 5;
    const int gxg = pg & 7;
    const int py = pg >> 3;
    const int co_base = cog * NCO;

    float acc[4][NCO];
#pragma unroll
    for (int j = 0; j < 4; j++)
#pragma unroll
        for (int c = 0; c < NCO; c++) acc[j][c] = 0.f;

    const float* inb = in + (size_t)b * CIN_ * HWSZ;

    for (int ci0 = 0; ci0 < CIN_; ci0 += CINC) {
        for (int idx = tid; idx < CINC * (TH + 2) * (TW + 2); idx += 256) {
            int c = idx / ((TH + 2) * (TW + 2));
            int rem = idx % ((TH + 2) * (TW + 2));
            int r = rem / (TW + 2), col = rem % (TW + 2);
            int iy = y0 + r - 1, ix = x0 + col - 1;
            float v = 0.f;
            if (iy >= 0 && iy < H_ && ix >= 0 && ix < W_)
                v = inb[(size_t)(ci0 + c) * HWSZ + iy * W_ + ix];
            s_in[(c * (TH + 2) + r) * SW + col] = v;
        }
        for (int idx = tid; idx < COUT_TILE * CINC * 9; idx += 256) {
            int co = idx / (CINC * 9);
            int rem = idx % (CINC * 9);
            s_w[idx] = wt[(size_t)(coB + co) * CIN_ * 9 + ci0 * 9 + rem];
        }
        __syncthreads();

#pragma unroll 2
        for (int cc = 0; cc < CINC; ++cc) {
            const float* si = &s_in[(cc * (TH + 2) + py) * SW + gxg];
            const float* swp = &s_w[co_base * (CINC * 9) + cc * 9];
#pragma unroll
            for (int ky = 0; ky < 3; ++ky) {
                float iv[3][4];
#pragma unroll
                for (int kx = 0; kx < 3; kx++)
#pragma unroll
                    for (int j = 0; j < 4; j++)
                        iv[kx][j] = si[ky * SW + kx + 8 * j];
#pragma unroll
                for (int kx = 0; kx < 3; kx++) {
#pragma unroll
                    for (int c = 0; c < NCO; c++) {
                        float wv = swp[c * (CINC * 9) + ky * 3 + kx];
#pragma unroll
                        for (int j = 0; j < 4; j++)
                            acc[j][c] = fmaf(iv[kx][j], wv, acc[j][c]);
                    }
                }
            }
        }
        __syncthreads();
    }

    const int yy = y0 + py;
#pragma unroll
    for (int c = 0; c < NCO; c++) {
        int co = coB + co_base + c;
        float bv = bias[co];
#pragma unroll
        for (int j = 0; j < 4; j++) {
            float v = acc[j][c] + bv;
            if (DO_GELU) v = gelu_f(v);
            out[((size_t)b * Cout + co) * HWSZ + yy * W_ + x0 + gxg + 8 * j] = v;
        }
    }
}

// ---------------- sampler (R1-proven) --------------------------------------------
__global__ __launch_bounds__(256) void sampler_kernel(
    const float* __restrict__ key, const float* __restrict__ ww2,
    const float* __restrict__ wb2)
{
    __shared__ float s_ww2[K_ * 32];
    __shared__ float s_wb2[K_];
    __shared__ float s_logit[K_][64];
    __shared__ int   s_o[K_][4][64];
    __shared__ float s_wt[K_][4][64];

    const int b = blockIdx.z, y = blockIdx.y, x0 = blockIdx.x * 64;
    const int tid = threadIdx.x;
    if (tid < K_ * 32) s_ww2[tid] = ww2[tid];
    if (tid < K_) s_wb2[tid] = wb2[tid];
    __syncthreads();

    const int px = tid & 63;
    const int k = tid >> 6;
    const int x = x0 + px;

    const float* offb = g_off + (size_t)b * 2 * K_ * HWSZ + y * W_ + x;
    float ox = offb[(size_t)(2 * k) * HWSZ];
    float oy = offb[(size_t)(2 * k + 1) * HWSZ];

    const float* w1b = g_w1 + (size_t)b * 32 * HWSZ + y * W_ + x;
    float l = s_wb2[k];
#pragma unroll 8
    for (int c = 0; c < 32; c++) l = fmaf(s_ww2[k * 32 + c], w1b[(size_t)c * HWSZ], l);
    s_logit[k][px] = l;

    float bx = -1.f + 2.f * x * (1.f / (W_ - 1));
    float by = -1.f + 2.f * y * (1.f / (H_ - 1));
    float gxn = fminf(fmaxf(bx + ox * (2.f / W_), -1.f), 1.f);
    float gyn = fminf(fmaxf(by + oy * (2.f / H_), -1.f), 1.f);
    float pxf = (gxn + 1.f) * 0.5f * (W_ - 1);
    float pyf = (gyn + 1.f) * 0.5f * (H_ - 1);
    pxf = fminf(fmaxf(pxf, 0.f), (float)(W_ - 1));
    pyf = fminf(fmaxf(pyf, 0.f), (float)(H_ - 1));
    int ix0 = min((int)floorf(pxf), W_ - 1);
    int iy0 = min((int)floorf(pyf), H_ - 1);
    int ix1 = min(ix0 + 1, W_ - 1);
    int iy1 = min(iy0 + 1, H_ - 1);
    float fx = pxf - (float)ix0, fy = pyf - (float)iy0;
    __syncthreads();

    float m = fmaxf(fmaxf(s_logit[0][px], s_logit[1][px]),
                    fmaxf(s_logit[2][px], s_logit[3][px]));
    float se = 0.f;
#pragma unroll
    for (int q = 0; q < K_; q++) se += expf(s_logit[q][px] - m);
    float wk = expf(l - m) / se;

    s_o[k][0][px] = iy0 * W_ + ix0;
    s_o[k][1][px] = iy0 * W_ + ix1;
    s_o[k][2][px] = iy1 * W_ + ix0;
    s_o[k][3][px] = iy1 * W_ + ix1;
    s_wt[k][0][px] = wk * (1.f - fx) * (1.f - fy);
    s_wt[k][1][px] = wk * fx * (1.f - fy);
    s_wt[k][2][px] = wk * (1.f - fx) * fy;
    s_wt[k][3][px] = wk * fx * fy;
    __syncthreads();

    int o[K_][4]; float w[K_][4];
#pragma unroll
    for (int q = 0; q < K_; q++)
#pragma unroll
        for (int t = 0; t < 4; t++) { o[q][t] = s_o[q][t][px]; w[q][t] = s_wt[q][t][px]; }

    const int cq = tid >> 6;
    const float* keyb = key + (size_t)b * CIN_ * HWSZ;
    float* aggb = g_agg + (size_t)b * CIN_ * HWSZ + y * W_ + x;
    for (int itc = 0; itc < 32; ++itc) {
        int c = itc * 4 + cq;
        const float* kp = keyb + (size_t)c * HWSZ;
        float a = 0.f;
#pragma unroll
        for (int q = 0; q < K_; q++) {
            a = fmaf(kp[o[q][0]], w[q][0], a);
            a = fmaf(kp[o[q][1]], w[q][1], a);
            a = fmaf(kp[o[q][2]], w[q][2], a);
            a = fmaf(kp[o[q][3]], w[q][3], a);
        }
        aggb[(size_t)c * HWSZ] = a;
    }
}

// ---------------- fusion (R1-proven scalar) ---------------------------------------
__global__ __launch_bounds__(256) void fusion_kernel(
    const float* __restrict__ query,
    const float* __restrict__ fw1, const float* __restrict__ fb1,
    const float* __restrict__ fw2, const float* __restrict__ fb2,
    float* __restrict__ out)
{
    constexpr int PX = 64, SXS = 66;
    __shared__ float s_x[128 * SXS];
    __shared__ float s_in[16 * PX];
    __shared__ float s_w[128 * 16];

    const int b = blockIdx.y;
    const int p0 = blockIdx.x * PX;
    const int tid = threadIdx.x;
    const int pg = tid & 15;
    const int cog = tid >> 4;
    const int co0 = cog * 8;

    const float* aggb = g_agg + (size_t)b * 128 * HWSZ + p0;

    float acc[4][8];
#pragma unroll
    for (int j = 0; j < 4; j++)
#pragma unroll
        for (int c = 0; c < 8; c++) acc[j][c] = 0.f;

    for (int ci0 = 0; ci0 < 128; ci0 += 16) {
        for (int idx = tid; idx < 16 * PX; idx += 256) {
            int c = idx >> 6, p = idx & 63;
            s_in[idx] = aggb[(size_t)(ci0 + c) * HWSZ + p];
        }
        for (int idx = tid; idx < 128 * 16; idx += 256) {
            int co = idx >> 4, ci = idx & 15;
            s_w[idx] = fw1[co * 128 + ci0 + ci];
        }
        __syncthreads();
#pragma unroll 4
        for (int ci = 0; ci < 16; ++ci) {
            float iv[4];
#pragma unroll
            for (int j = 0; j < 4; j++) iv[j] = s_in[ci * PX + pg + 16 * j];
#pragma unroll
            for (int c = 0; c < 8; c++) {
                float wv = s_w[(co0 + c) * 16 + ci];
#pragma unroll
                for (int j = 0; j < 4; j++) acc[j][c] = fmaf(iv[j], wv, acc[j][c]);
            }
        }
        __syncthreads();
    }
#pragma unroll
    for (int c = 0; c < 8; c++) {
        float bv = fb1[co0 + c];
#pragma unroll
        for (int j = 0; j < 4; j++)
            s_x[(co0 + c) * SXS + pg + 16 * j] = gelu_f(acc[j][c] + bv);
    }
    __syncthreads();

    float acc2[4][8];
#pragma unroll
    for (int j = 0; j < 4; j++)
#pragma unroll
        for (int c = 0; c < 8; c++) acc2[j][c] = 0.f;

    for (int ci0 = 0; ci0 < 128; ci0 += 16) {
        for (int idx = tid; idx < 128 * 16; idx += 256) {
            int co = idx >> 4, ci = idx & 15;
            s_w[idx] = fw2[co * 128 + ci0 + ci];
        }
        __syncthreads();
#pragma unroll 4
        for (int ci = 0; ci < 16; ++ci) {
            float iv[4];
#pragma unroll
            for (int j = 0; j < 4; j++) iv[j] = s_x[(ci0 + ci) * SXS + pg + 16 * j];
#pragma unroll
            for (int c = 0; c < 8; c++) {
                float wv = s_w[(co0 + c) * 16 + ci];
#pragma unroll
                for (int j = 0; j < 4; j++) acc2[j][c] = fmaf(iv[j], wv, acc2[j][c]);
            }
        }
        __syncthreads();
    }

    const float* qb = query + (size_t)b * 128 * HWSZ + p0;
    float* ob = out + (size_t)b * 128 * HWSZ + p0;
#pragma unroll
    for (int c = 0; c < 8; c++) {
        float bv = fb2[co0 + c];
#pragma unroll
        for (int j = 0; j < 4; j++) {
            size_t idx = (size_t)(co0 + c) * HWSZ + pg + 16 * j;
            ob[idx] = qb[idx] + 0.3f * (acc2[j][c] + bv);
        }
    }
}

// ---------------- launch ----------------
extern "C" void kernel_launch(void* const* d_in, const int* in_sizes, int n_in,
                              void* d_out, int out_size)
{
    const float* query = (const float*)d_in[0];
    const float* key   = (const float*)d_in[1];
    const float* ow1 = (const float*)d_in[2];
    const float* ob1 = (const float*)d_in[3];
    const float* ow2 = (const float*)d_in[4];
    const float* ob2 = (const float*)d_in[5];
    const float* ww1 = (const float*)d_in[6];
    const float* wb1 = (const float*)d_in[7];
    const float* ww2 = (const float*)d_in[8];
    const float* wb2 = (const float*)d_in[9];
    const float* fw1 = (const float*)d_in[10];
    const float* fb1 = (const float*)d_in[11];
    const float* fw2 = (const float*)d_in[12];
    const float* fb2 = (const float*)d_in[13];
    float* out = (float*)d_out;

    float *t1p, *offp, *w1p;
    cudaGetSymbolAddress((void**)&t1p, g_t1);
    cudaGetSymbolAddress((void**)&offp, g_off);
    cudaGetSymbolAddress((void**)&w1p, g_w1);

    cudaFuncSetAttribute(conv1_mma_kernel,
                         cudaFuncAttributeMaxDynamicSharedMemorySize, SMEM_MMA);

    dim3 blk(256);
    // prep split weights for conv1
    prep_wA_kernel<<<288, 256>>>(ow1);
    // t1 = gelu(conv3x3(query, ow1)) via mma.sync bf16 3-term
    conv1_mma_kernel<<<dim3(4, 128, B_), blk, SMEM_MMA>>>(query, ob1, t1p);
    // offsets = conv3x3(t1, ow2)   Cout=8  (scalar)
    conv3x3_kernel<8, 1, false><<<dim3(512, 1, B_), blk>>>(t1p, ow2, ob2, offp, 8);
    // w1 = gelu(conv3x3(query, ww1))  Cout=32 (scalar)
    conv3x3_kernel<32, 4, true><<<dim3(512, 1, B_), blk>>>(query, ww1, wb1, w1p, 32);
    // sampler
    sampler_kernel<<<dim3(W_ / 64, H_, B_), blk>>>(key, ww2, wb2);
    // fusion
    fusion_kernel<<<dim3(HWSZ / 64, B_), blk>>>(query, fw1, fb1, fw2, fb2, out);
}